// round 4
// baseline (speedup 1.0000x reference)
#include <cuda_runtime.h>
#include <cuda_bf16.h>
#include <math.h>

#define MAXB 8192
#define WPC 4   // warps per CTA in fallback solve

__device__ float g_pen[MAXB];
__device__ int   g_flag[MAXB];

__device__ __forceinline__ float sg(float x) { return 1.f / (1.f + __expf(-x)); }

// ============================================================================
// Kernel 1: LDL^T inertia of (M - 0.1 I). One CTA (64 threads) per matrix,
// one row per lane in registers. Counts negative pivots; if < 2 the penalty is
// exactly 0 (lambda_2 >= 0.1). Otherwise flags the matrix for the fallback
// eigensolver. Fully unrolled pivot loop: static indices, no reductions.
// ============================================================================
__global__ void __launch_bounds__(64, 8)
ldl_inertia_kernel(const float* __restrict__ E, int B)
{
    const int b = blockIdx.x;
    if (b >= B) return;
    const int t = threadIdx.x;

    __shared__ __align__(16) float svb[2][64];

    const float* Eb = E + (size_t)b * 4096;
    float a[64];

    // ---- Build row t of M - 0.1I ----
    // Lower part (j < t) from own row; upper part (j > t) mirrored from rows j
    // (lower-triangle symmetrization, matching eigvalsh UPLO='L').
    float rs = 0.f, ds = 0.f;
    #pragma unroll
    for (int j0 = 0; j0 < 64; j0 += 4) {
        float4 e4 = *(const float4*)(Eb + (size_t)t * 64 + j0);
        float s;
        s = sg(e4.x); rs += s; if (j0 + 0 < t) a[j0 + 0] = -s; if (j0 + 0 == t) ds = s;
        s = sg(e4.y); rs += s; if (j0 + 1 < t) a[j0 + 1] = -s; if (j0 + 1 == t) ds = s;
        s = sg(e4.z); rs += s; if (j0 + 2 < t) a[j0 + 2] = -s; if (j0 + 2 == t) ds = s;
        s = sg(e4.w); rs += s; if (j0 + 3 < t) a[j0 + 3] = -s; if (j0 + 3 == t) ds = s;
    }
    #pragma unroll
    for (int j = 1; j < 64; j++) {
        float ev = Eb[(size_t)j * 64 + t];   // coalesced across lanes at fixed j
        if (j > t) a[j] = -sg(ev);
    }
    {
        float dg = rs - ds - 0.1f;
        #pragma unroll
        for (int j = 0; j < 64; j++)
            if (j == t) a[j] = dg;
    }

    // ---- Unpivoted LDL^T, counting negative pivots ----
    int cnt = 0;
    float c = a[0];           // current column-k value of this lane's row

    #pragma unroll
    for (int k = 0; k < 64; k++) {
        float* sv = svb[k & 1];
        if (t >= k) sv[t] = c;
        __syncthreads();      // one barrier per step (double-buffered sv)

        float p = sv[k];
        float pg = (fabsf(p) < 1e-30f) ? ((p < 0.f) ? -1e-30f : 1e-30f) : p;
        cnt += (pg < 0.f) ? 1 : 0;

        if (k < 63) {
            const int m0 = k + 1;
            if (t >= m0) {
                float s = __fdividef(c, pg);
                const int j0 = m0 & ~3;       // float4-aligned start
                float nc = 0.f;
                #pragma unroll
                for (int j = j0; j < 64; j += 4) {
                    float4 v4 = *(const float4*)&sv[j];
                    float x;
                    x = a[j + 0] - s * v4.x; a[j + 0] = x; if (j + 0 == m0) nc = x;
                    x = a[j + 1] - s * v4.y; a[j + 1] = x; if (j + 1 == m0) nc = x;
                    x = a[j + 2] - s * v4.z; a[j + 2] = x; if (j + 2 == m0) nc = x;
                    x = a[j + 3] - s * v4.w; a[j + 3] = x; if (j + 3 == m0) nc = x;
                }
                c = nc;
            }
        }
    }

    if (t == 0) {
        int need = (cnt >= 2) ? 1 : 0;
        g_flag[b] = need;
        g_pen[b]  = 0.f;      // overwritten by fallback if need
    }
}

// ============================================================================
// Kernel 2 (fallback, gated): warp-per-matrix Householder tridiagonalization +
// Sturm multisection for lambda_2. Only runs for flagged matrices.
// ============================================================================
__global__ void __launch_bounds__(32 * WPC)
spectral_solve_kernel(const float* __restrict__ E, int B)
{
    const int lane = threadIdx.x & 31;
    const int w    = threadIdx.x >> 5;
    const int b    = blockIdx.x * WPC + w;
    if (b >= B) return;
    if (g_flag[b] == 0) return;

    __shared__ __align__(16) float sv [WPC][64];
    __shared__ __align__(16) float sw_[WPC][64];
    __shared__ float sdd[WPC][64];
    __shared__ float see[WPC][64];

    const int rL = lane, rH = lane + 32;
    const float* Eb = E + (size_t)b * 4096;

    float aL[64], aH[64];

    float degL = 0.f, degH = 0.f, dsL = 0.f, dsH = 0.f;
    #pragma unroll
    for (int j0 = 0; j0 < 64; j0 += 4) {
        float4 eL = *(const float4*)(Eb + (size_t)rL * 64 + j0);
        float4 eH = *(const float4*)(Eb + (size_t)rH * 64 + j0);
        float s;
        s = sg(eL.x); degL += s; if (j0+0 <  rL) aL[j0+0] = -s; if (j0+0 == rL) dsL = s;
        s = sg(eL.y); degL += s; if (j0+1 <  rL) aL[j0+1] = -s; if (j0+1 == rL) dsL = s;
        s = sg(eL.z); degL += s; if (j0+2 <  rL) aL[j0+2] = -s; if (j0+2 == rL) dsL = s;
        s = sg(eL.w); degL += s; if (j0+3 <  rL) aL[j0+3] = -s; if (j0+3 == rL) dsL = s;
        s = sg(eH.x); degH += s; if (j0+0 <  rH) aH[j0+0] = -s; if (j0+0 == rH) dsH = s;
        s = sg(eH.y); degH += s; if (j0+1 <  rH) aH[j0+1] = -s; if (j0+1 == rH) dsH = s;
        s = sg(eH.z); degH += s; if (j0+2 <  rH) aH[j0+2] = -s; if (j0+2 == rH) dsH = s;
        s = sg(eH.w); degH += s; if (j0+3 <  rH) aH[j0+3] = -s; if (j0+3 == rH) dsH = s;
    }
    #pragma unroll
    for (int j = 1; j < 64; j++) {
        float eu = Eb[(size_t)j * 64 + rL];
        if (j > rL) aL[j] = -sg(eu);
        if (j >= 33) {
            float eu2 = Eb[(size_t)j * 64 + rH];
            if (j > rH) aH[j] = -sg(eu2);
        }
    }
    {
        float dL = degL - dsL, dH = degH - dsH;
        #pragma unroll
        for (int j = 0; j < 64; j++) {
            if (j == rL) aL[j] = dL;
            if (j == rH) aH[j] = dH;
        }
    }

    float xiL = aL[0];
    float xiH = aH[0];

    for (int k = 0; k < 62; k++) {
        const int m0 = k + 1;

        float cL = (rL >= m0) ? xiL : 0.f;
        float cH = (rH >= m0) ? xiH : 0.f;
        float sig = cL * cL + cH * cH;
        #pragma unroll
        for (int o = 16; o > 0; o >>= 1) sig += __shfl_xor_sync(0xffffffffu, sig, o);

        float cand = (m0 < 32) ? xiL : xiH;
        float x0 = __shfl_sync(0xffffffffu, cand, m0 & 31);

        float normx = sqrtf(sig);
        bool  skip  = (normx < 1e-18f);
        float alpha = (x0 >= 0.f) ? -normx : normx;
        float beta  = skip ? 0.f : 1.f / (normx * (normx + fabsf(x0)));

        if (lane == 0) see[w][k] = skip ? 0.f : alpha;
        if (rL == k)   sdd[w][k] = xiL;
        if (rH == k)   sdd[w][k] = xiH;

        float vL = (rL > m0) ? xiL : ((rL == m0) ? (x0 - alpha) : 0.f);
        float vH = (rH > m0) ? xiH : ((rH == m0) ? (x0 - alpha) : 0.f);
        sv[w][rL] = vL;
        sv[w][rH] = vH;
        __syncwarp();

        const int c0 = m0 >> 4;
        float pL0 = 0.f, pL1 = 0.f, pH0 = 0.f, pH1 = 0.f;
        #pragma unroll
        for (int c = 0; c < 4; c++) {
            if (c >= c0) {
                #pragma unroll
                for (int u = 0; u < 16; u += 4) {
                    const int j = 16 * c + u;
                    float4 v4 = *(const float4*)&sv[w][j];
                    pL0 += aL[j]     * v4.x + aL[j + 1] * v4.y;
                    pL1 += aL[j + 2] * v4.z + aL[j + 3] * v4.w;
                    pH0 += aH[j]     * v4.x + aH[j + 1] * v4.y;
                    pH1 += aH[j + 2] * v4.z + aH[j + 3] * v4.w;
                }
            }
        }
        float pL = (rL >= m0) ? (pL0 + pL1) * beta : 0.f;
        float pH = (rH >= m0) ? (pH0 + pH1) * beta : 0.f;

        float Ks = vL * pL + vH * pH;
        #pragma unroll
        for (int o = 16; o > 0; o >>= 1) Ks += __shfl_xor_sync(0xffffffffu, Ks, o);
        float K  = 0.5f * Ks;
        float wL = pL - K * vL;
        float wH = pH - K * vH;
        __syncwarp();
        sw_[w][rL] = wL;
        sw_[w][rH] = wH;
        __syncwarp();

        float nL = 0.f, nH = 0.f;
        #pragma unroll
        for (int c = 0; c < 4; c++) {
            if (c >= c0) {
                #pragma unroll
                for (int u = 0; u < 16; u += 4) {
                    const int j = 16 * c + u;
                    float4 v4 = *(const float4*)&sv[w][j];
                    float4 w4 = *(const float4*)&sw_[w][j];
                    float x;
                    x = aL[j]   - (vL * w4.x + wL * v4.x); aL[j]   = x; if (j     == m0) nL = x;
                    x = aL[j+1] - (vL * w4.y + wL * v4.y); aL[j+1] = x; if (j + 1 == m0) nL = x;
                    x = aL[j+2] - (vL * w4.z + wL * v4.z); aL[j+2] = x; if (j + 2 == m0) nL = x;
                    x = aL[j+3] - (vL * w4.w + wL * v4.w); aL[j+3] = x; if (j + 3 == m0) nL = x;
                    x = aH[j]   - (vH * w4.x + wH * v4.x); aH[j]   = x; if (j     == m0) nH = x;
                    x = aH[j+1] - (vH * w4.y + wH * v4.y); aH[j+1] = x; if (j + 1 == m0) nH = x;
                    x = aH[j+2] - (vH * w4.z + wH * v4.z); aH[j+2] = x; if (j + 2 == m0) nH = x;
                    x = aH[j+3] - (vH * w4.w + wH * v4.w); aH[j+3] = x; if (j + 3 == m0) nH = x;
                }
            }
        }
        xiL = nL;
        xiH = nH;
        __syncwarp();
    }

    if (rH == 62) sdd[w][62] = xiH;
    if (rH == 63) {
        see[w][62] = xiH;
        sdd[w][63] = aH[63];
        see[w][63] = 0.f;
    }
    __syncwarp();

    sw_[w][rL] = see[w][rL] * see[w][rL];
    sw_[w][rH] = see[w][rH] * see[w][rH];
    __syncwarp();

    float dLv = sdd[w][rL], dHv = sdd[w][rH];
    float radL = ((rL > 0) ? fabsf(see[w][rL - 1]) : 0.f) + fabsf(see[w][rL]);
    float radH = fabsf(see[w][rH - 1]) + ((rH < 63) ? fabsf(see[w][rH]) : 0.f);
    float lo = fminf(dLv - radL, dHv - radH);
    float hi = fmaxf(dLv + radL, dHv + radH);
    #pragma unroll
    for (int o = 16; o > 0; o >>= 1) {
        lo = fminf(lo, __shfl_xor_sync(0xffffffffu, lo, o));
        hi = fmaxf(hi, __shfl_xor_sync(0xffffffffu, hi, o));
    }

    #pragma unroll 1
    for (int round = 0; round < 5; round++) {
        float stepw = (hi - lo) * (1.f / 33.f);
        float x = lo + stepw * (float)(lane + 1);
        int cnt = 0;
        float q = sdd[w][0] - x;
        if (q < 0.f) cnt++;
        #pragma unroll 1
        for (int i = 1; i < 64; i++) {
            float denom = q;
            if (fabsf(denom) < 1e-25f) denom = (denom < 0.f) ? -1e-25f : 1e-25f;
            q = (sdd[w][i] - x) - __fdividef(sw_[w][i - 1], denom);
            if (q < 0.f) cnt++;
        }
        unsigned bal = __ballot_sync(0xffffffffu, cnt >= 2);
        if (bal == 0u) {
            lo = lo + stepw * 32.f;
        } else {
            int j = __ffs(bal) - 1;
            float nhi = lo + stepw * (float)(j + 1);
            float nlo = (j > 0) ? (lo + stepw * (float)j) : lo;
            hi = nhi; lo = nlo;
        }
    }
    if (lane == 0) {
        float lam2 = 0.5f * (lo + hi);
        float p = 0.1f - lam2;
        g_pen[b] = (p > 0.f) ? p : 0.f;
    }
}

// ============================================================================
// Kernel 3: deterministic final reduction.
// ============================================================================
__global__ void __launch_bounds__(256)
spectral_reduce_kernel(float* __restrict__ out, int B)
{
    __shared__ float red[256];
    int t = threadIdx.x;
    float s = 0.f;
    for (int i = t; i < B; i += 256) s += g_pen[i];
    red[t] = s;
    __syncthreads();
    #pragma unroll
    for (int o = 128; o >= 1; o >>= 1) {
        if (t < o) red[t] += red[t + o];
        __syncthreads();
    }
    if (t == 0) out[0] = red[0] / (float)B;
}

extern "C" void kernel_launch(void* const* d_in, const int* in_sizes, int n_in,
                              void* d_out, int out_size)
{
    const float* E = (const float*)d_in[0];
    int B = in_sizes[0] / 4096;
    if (B > MAXB) B = MAXB;

    ldl_inertia_kernel<<<B, 64>>>(E, B);
    int grid2 = (B + WPC - 1) / WPC;
    spectral_solve_kernel<<<grid2, 32 * WPC>>>(E, B);
    spectral_reduce_kernel<<<1, 256>>>((float*)d_out, B);
}

// round 5
// speedup vs baseline: 34.1658x; 34.1658x over previous
#include <cuda_runtime.h>
#include <cuda_bf16.h>
#include <math.h>

#define MAXB 8192
#define WPC 4   // warps per CTA in fallback solve

__device__ float g_pen[MAXB];
__device__ int   g_flag[MAXB];

__device__ __forceinline__ float sg(float x) { return 1.f / (1.f + __expf(-x)); }

// ============================================================================
// Kernel 1: transcendental-free certificate that lambda_2 >= 0.1.
//
// Let M = lower-symmetrized (diag(deg) - sigmoid(E)) as eigvalsh(L) sees it.
// P = (M - 0.1 I) + 0.5 * ones*ones^T  (positive rank-1 => lambda_1(P) <= lambda_2(M-0.1I)).
// If Gershgorin lower bound of P >= 0 then penalty = 0 exactly.
// Sigmoid bounds (rigorous, piecewise-linear):
//   |sigma(x)-0.5| <= min(|x|/4, 0.5)              (off-diagonal magnitude)
//   sigma(x) >= clamp(0.5 + x/4, 0, 0.5)           (degree lower bound)
//   sigma(x) <= min(0.5 + max(x,0)/4, 1)           (self-loop upper bound)
// Rows that fail get the exact eigensolver fallback.
// ============================================================================
__global__ void __launch_bounds__(64)
certify_kernel(const float* __restrict__ E, int B)
{
    const int b = blockIdx.x;
    if (b >= B) return;
    const int t = threadIdx.x;

    __shared__ float A[64][65];     // pad 65: row & column passes conflict-free
    __shared__ float warpmin[2];

    const float* Eb = E + (size_t)b * 4096;

    // ---- Cooperative load: 1024 float4 (coalesced), scalar stores to smem ----
    const float4* E4 = (const float4*)Eb;
    #pragma unroll
    for (int i = 0; i < 16; i++) {
        int idx = i * 64 + t;             // float4 index
        float4 v = E4[idx];
        int el = idx * 4;
        int row = el >> 6;
        int col = el & 63;
        A[row][col + 0] = v.x;
        A[row][col + 1] = v.y;
        A[row][col + 2] = v.z;
        A[row][col + 3] = v.w;
    }
    __syncthreads();

    // ---- Row pass: degree lower bound + lower-triangle radius + self upper ----
    float deg_lo = 0.f;
    float rad    = 0.f;
    float u_self = 0.f;
    #pragma unroll 8
    for (int j = 0; j < 64; j++) {
        float x = A[t][j];                           // banks (t + j) % 32: conflict-free
        // l(x) = clamp(0.5 + 0.25x, 0, 0.5)
        deg_lo += fminf(fmaxf(fmaf(0.25f, x, 0.5f), 0.f), 0.5f);
        float m = fminf(0.25f * fabsf(x), 0.5f);
        if (j < t)  rad += m;                        // lower-sym uses E[t][j], j<t
        if (j == t) u_self = fminf(fmaf(0.25f, fmaxf(x, 0.f), 0.5f), 1.f);
    }

    // ---- Column pass: upper-triangle radius from mirrored entries E[j][t], j>t ----
    #pragma unroll 8
    for (int j = 0; j < 64; j++) {
        float x = A[j][t];                           // banks (j + t) % 32: conflict-free
        float m = fminf(0.25f * fabsf(x), 0.5f);
        if (j > t) rad += m;
    }

    // bound_t = P_tt(lower) - R_t(upper);  P_tt = deg - sigma_tt - 0.1 + 0.5
    float bound = (deg_lo - u_self + 0.4f) - rad;

    // ---- CTA min over 64 rows ----
    #pragma unroll
    for (int o = 16; o > 0; o >>= 1)
        bound = fminf(bound, __shfl_xor_sync(0xffffffffu, bound, o));
    if ((t & 31) == 0) warpmin[t >> 5] = bound;
    __syncthreads();
    if (t == 0) {
        float mn = fminf(warpmin[0], warpmin[1]);
        g_flag[b] = (mn < 0.f) ? 1 : 0;
        g_pen[b]  = 0.f;                 // exact solver overwrites if flagged
    }
}

// ============================================================================
// Kernel 2 (fallback, gated): warp-per-matrix Householder tridiagonalization +
// Sturm multisection for lambda_2. Runs only for flagged matrices.
// ============================================================================
__global__ void __launch_bounds__(32 * WPC)
spectral_solve_kernel(const float* __restrict__ E, int B)
{
    const int lane = threadIdx.x & 31;
    const int w    = threadIdx.x >> 5;
    const int b    = blockIdx.x * WPC + w;
    if (b >= B) return;
    if (g_flag[b] == 0) return;

    __shared__ __align__(16) float sv [WPC][64];
    __shared__ __align__(16) float sw_[WPC][64];
    __shared__ float sdd[WPC][64];
    __shared__ float see[WPC][64];

    const int rL = lane, rH = lane + 32;
    const float* Eb = E + (size_t)b * 4096;

    float aL[64], aH[64];

    float degL = 0.f, degH = 0.f, dsL = 0.f, dsH = 0.f;
    #pragma unroll
    for (int j0 = 0; j0 < 64; j0 += 4) {
        float4 eL = *(const float4*)(Eb + (size_t)rL * 64 + j0);
        float4 eH = *(const float4*)(Eb + (size_t)rH * 64 + j0);
        float s;
        s = sg(eL.x); degL += s; if (j0+0 <  rL) aL[j0+0] = -s; if (j0+0 == rL) dsL = s;
        s = sg(eL.y); degL += s; if (j0+1 <  rL) aL[j0+1] = -s; if (j0+1 == rL) dsL = s;
        s = sg(eL.z); degL += s; if (j0+2 <  rL) aL[j0+2] = -s; if (j0+2 == rL) dsL = s;
        s = sg(eL.w); degL += s; if (j0+3 <  rL) aL[j0+3] = -s; if (j0+3 == rL) dsL = s;
        s = sg(eH.x); degH += s; if (j0+0 <  rH) aH[j0+0] = -s; if (j0+0 == rH) dsH = s;
        s = sg(eH.y); degH += s; if (j0+1 <  rH) aH[j0+1] = -s; if (j0+1 == rH) dsH = s;
        s = sg(eH.z); degH += s; if (j0+2 <  rH) aH[j0+2] = -s; if (j0+2 == rH) dsH = s;
        s = sg(eH.w); degH += s; if (j0+3 <  rH) aH[j0+3] = -s; if (j0+3 == rH) dsH = s;
    }
    #pragma unroll
    for (int j = 1; j < 64; j++) {
        float eu = Eb[(size_t)j * 64 + rL];
        if (j > rL) aL[j] = -sg(eu);
        if (j >= 33) {
            float eu2 = Eb[(size_t)j * 64 + rH];
            if (j > rH) aH[j] = -sg(eu2);
        }
    }
    {
        float dL = degL - dsL, dH = degH - dsH;
        #pragma unroll
        for (int j = 0; j < 64; j++) {
            if (j == rL) aL[j] = dL;
            if (j == rH) aH[j] = dH;
        }
    }

    float xiL = aL[0];
    float xiH = aH[0];

    for (int k = 0; k < 62; k++) {
        const int m0 = k + 1;

        float cL = (rL >= m0) ? xiL : 0.f;
        float cH = (rH >= m0) ? xiH : 0.f;
        float sig = cL * cL + cH * cH;
        #pragma unroll
        for (int o = 16; o > 0; o >>= 1) sig += __shfl_xor_sync(0xffffffffu, sig, o);

        float cand = (m0 < 32) ? xiL : xiH;
        float x0 = __shfl_sync(0xffffffffu, cand, m0 & 31);

        float normx = sqrtf(sig);
        bool  skip  = (normx < 1e-18f);
        float alpha = (x0 >= 0.f) ? -normx : normx;
        float beta  = skip ? 0.f : 1.f / (normx * (normx + fabsf(x0)));

        if (lane == 0) see[w][k] = skip ? 0.f : alpha;
        if (rL == k)   sdd[w][k] = xiL;
        if (rH == k)   sdd[w][k] = xiH;

        float vL = (rL > m0) ? xiL : ((rL == m0) ? (x0 - alpha) : 0.f);
        float vH = (rH > m0) ? xiH : ((rH == m0) ? (x0 - alpha) : 0.f);
        sv[w][rL] = vL;
        sv[w][rH] = vH;
        __syncwarp();

        const int c0 = m0 >> 4;
        float pL0 = 0.f, pL1 = 0.f, pH0 = 0.f, pH1 = 0.f;
        #pragma unroll
        for (int c = 0; c < 4; c++) {
            if (c >= c0) {
                #pragma unroll
                for (int u = 0; u < 16; u += 4) {
                    const int j = 16 * c + u;
                    float4 v4 = *(const float4*)&sv[w][j];
                    pL0 += aL[j]     * v4.x + aL[j + 1] * v4.y;
                    pL1 += aL[j + 2] * v4.z + aL[j + 3] * v4.w;
                    pH0 += aH[j]     * v4.x + aH[j + 1] * v4.y;
                    pH1 += aH[j + 2] * v4.z + aH[j + 3] * v4.w;
                }
            }
        }
        float pL = (rL >= m0) ? (pL0 + pL1) * beta : 0.f;
        float pH = (rH >= m0) ? (pH0 + pH1) * beta : 0.f;

        float Ks = vL * pL + vH * pH;
        #pragma unroll
        for (int o = 16; o > 0; o >>= 1) Ks += __shfl_xor_sync(0xffffffffu, Ks, o);
        float K  = 0.5f * Ks;
        float wL = pL - K * vL;
        float wH = pH - K * vH;
        __syncwarp();
        sw_[w][rL] = wL;
        sw_[w][rH] = wH;
        __syncwarp();

        float nL = 0.f, nH = 0.f;
        #pragma unroll
        for (int c = 0; c < 4; c++) {
            if (c >= c0) {
                #pragma unroll
                for (int u = 0; u < 16; u += 4) {
                    const int j = 16 * c + u;
                    float4 v4 = *(const float4*)&sv[w][j];
                    float4 w4 = *(const float4*)&sw_[w][j];
                    float x;
                    x = aL[j]   - (vL * w4.x + wL * v4.x); aL[j]   = x; if (j     == m0) nL = x;
                    x = aL[j+1] - (vL * w4.y + wL * v4.y); aL[j+1] = x; if (j + 1 == m0) nL = x;
                    x = aL[j+2] - (vL * w4.z + wL * v4.z); aL[j+2] = x; if (j + 2 == m0) nL = x;
                    x = aL[j+3] - (vL * w4.w + wL * v4.w); aL[j+3] = x; if (j + 3 == m0) nL = x;
                    x = aH[j]   - (vH * w4.x + wH * v4.x); aH[j]   = x; if (j     == m0) nH = x;
                    x = aH[j+1] - (vH * w4.y + wH * v4.y); aH[j+1] = x; if (j + 1 == m0) nH = x;
                    x = aH[j+2] - (vH * w4.z + wH * v4.z); aH[j+2] = x; if (j + 2 == m0) nH = x;
                    x = aH[j+3] - (vH * w4.w + wH * v4.w); aH[j+3] = x; if (j + 3 == m0) nH = x;
                }
            }
        }
        xiL = nL;
        xiH = nH;
        __syncwarp();
    }

    if (rH == 62) sdd[w][62] = xiH;
    if (rH == 63) {
        see[w][62] = xiH;
        sdd[w][63] = aH[63];
        see[w][63] = 0.f;
    }
    __syncwarp();

    sw_[w][rL] = see[w][rL] * see[w][rL];
    sw_[w][rH] = see[w][rH] * see[w][rH];
    __syncwarp();

    float dLv = sdd[w][rL], dHv = sdd[w][rH];
    float radL = ((rL > 0) ? fabsf(see[w][rL - 1]) : 0.f) + fabsf(see[w][rL]);
    float radH = fabsf(see[w][rH - 1]) + ((rH < 63) ? fabsf(see[w][rH]) : 0.f);
    float lo = fminf(dLv - radL, dHv - radH);
    float hi = fmaxf(dLv + radL, dHv + radH);
    #pragma unroll
    for (int o = 16; o > 0; o >>= 1) {
        lo = fminf(lo, __shfl_xor_sync(0xffffffffu, lo, o));
        hi = fmaxf(hi, __shfl_xor_sync(0xffffffffu, hi, o));
    }

    #pragma unroll 1
    for (int round = 0; round < 5; round++) {
        float stepw = (hi - lo) * (1.f / 33.f);
        float x = lo + stepw * (float)(lane + 1);
        int cnt = 0;
        float q = sdd[w][0] - x;
        if (q < 0.f) cnt++;
        #pragma unroll 1
        for (int i = 1; i < 64; i++) {
            float denom = q;
            if (fabsf(denom) < 1e-25f) denom = (denom < 0.f) ? -1e-25f : 1e-25f;
            q = (sdd[w][i] - x) - __fdividef(sw_[w][i - 1], denom);
            if (q < 0.f) cnt++;
        }
        unsigned bal = __ballot_sync(0xffffffffu, cnt >= 2);
        if (bal == 0u) {
            lo = lo + stepw * 32.f;
        } else {
            int j = __ffs(bal) - 1;
            float nhi = lo + stepw * (float)(j + 1);
            float nlo = (j > 0) ? (lo + stepw * (float)j) : lo;
            hi = nhi; lo = nlo;
        }
    }
    if (lane == 0) {
        float lam2 = 0.5f * (lo + hi);
        float p = 0.1f - lam2;
        g_pen[b] = (p > 0.f) ? p : 0.f;
    }
}

// ============================================================================
// Kernel 3: deterministic final reduction.
// ============================================================================
__global__ void __launch_bounds__(256)
spectral_reduce_kernel(float* __restrict__ out, int B)
{
    __shared__ float red[256];
    int t = threadIdx.x;
    float s = 0.f;
    for (int i = t; i < B; i += 256) s += g_pen[i];
    red[t] = s;
    __syncthreads();
    #pragma unroll
    for (int o = 128; o >= 1; o >>= 1) {
        if (t < o) red[t] += red[t + o];
        __syncthreads();
    }
    if (t == 0) out[0] = red[0] / (float)B;
}

extern "C" void kernel_launch(void* const* d_in, const int* in_sizes, int n_in,
                              void* d_out, int out_size)
{
    const float* E = (const float*)d_in[0];
    int B = in_sizes[0] / 4096;
    if (B > MAXB) B = MAXB;

    certify_kernel<<<B, 64>>>(E, B);
    int grid2 = (B + WPC - 1) / WPC;
    spectral_solve_kernel<<<grid2, 32 * WPC>>>(E, B);
    spectral_reduce_kernel<<<1, 256>>>((float*)d_out, B);
}

// round 7
// speedup vs baseline: 64.9217x; 1.9002x over previous
#include <cuda_runtime.h>
#include <cuda_bf16.h>
#include <math.h>

#define MAXB 8192
#define WPC 4   // warps per CTA in fallback solve

__device__ int g_flag[MAXB];

__device__ __forceinline__ float sg(float x) { return 1.f / (1.f + __expf(-x)); }

// ============================================================================
// Kernel 1: transcendental-free certificate that lambda_2 >= 0.1, single pass.
//
// M = lower-symmetrized (diag(deg) - sigmoid(E));  P = (M - 0.1I) + 0.5*ones^T.
// lambda_1(P) <= lambda_2(M - 0.1I)  (positive rank-1 interlacing).
// Gershgorin row bound on P with piecewise-linear sigmoid bounds:
//   deg_t >= sum_j clamp(0.5 + E[t][j]/4, 0, 0.5)        (deg_lo)
//   |0.5 - sigma(x)| <= min(|x|/4, 0.5)                  (m)
//   sigma_tt <= 1
// bound_t = deg_lo_t - 0.6 - rad_t,   rad_t = sum_{c<t} m(E[t][c]) + sum_{r>t} m(E[r][t])
// Element (r,c), r>c contributes m to BOTH rad_r (row part) and rad_c (col part)
// => one predicate, accumulated from registers during the coalesced load.
// ============================================================================
__global__ void __launch_bounds__(128, 8)
certify_kernel(const float* __restrict__ E, int B)
{
    const int b = blockIdx.x;
    if (b >= B) return;
    const int t = threadIdx.x;
    const int q = t & 15;    // column quad: columns 4q..4q+3
    const int g = t >> 4;    // row group 0..7: rows 8i+g

    __shared__ float P[64][17][2];   // [row][q][{deg,rad}]  (pad 17 vs banks)
    __shared__ float colP[8][64];    // [g][col] partial column radii
    __shared__ float warpmin[4];

    const float* Eb = E + (size_t)b * 4096;
    const float4* E4 = (const float4*)Eb;
    const int c0 = 4 * q;

    float col0 = 0.f, col1 = 0.f, col2 = 0.f, col3 = 0.f;

    #pragma unroll
    for (int i = 0; i < 8; i++) {
        float4 v = E4[i * 128 + t];          // fully coalesced
        const int r = 8 * i + g;
        float dacc = 0.f, racc = 0.f;
        float t1, m;

        t1 = fmaf(0.25f, v.x, 0.5f);
        dacc += fminf(fmaxf(t1, 0.f), 0.5f);
        m = fminf(fabsf(t1 - 0.5f), 0.5f);
        if (r > c0 + 0) { racc += m; col0 += m; }

        t1 = fmaf(0.25f, v.y, 0.5f);
        dacc += fminf(fmaxf(t1, 0.f), 0.5f);
        m = fminf(fabsf(t1 - 0.5f), 0.5f);
        if (r > c0 + 1) { racc += m; col1 += m; }

        t1 = fmaf(0.25f, v.z, 0.5f);
        dacc += fminf(fmaxf(t1, 0.f), 0.5f);
        m = fminf(fabsf(t1 - 0.5f), 0.5f);
        if (r > c0 + 2) { racc += m; col2 += m; }

        t1 = fmaf(0.25f, v.w, 0.5f);
        dacc += fminf(fmaxf(t1, 0.f), 0.5f);
        m = fminf(fabsf(t1 - 0.5f), 0.5f);
        if (r > c0 + 3) { racc += m; col3 += m; }

        P[r][q][0] = dacc;
        P[r][q][1] = racc;
    }
    colP[g][c0 + 0] = col0;
    colP[g][c0 + 1] = col1;
    colP[g][c0 + 2] = col2;
    colP[g][c0 + 3] = col3;
    __syncthreads();

    // ---- Phase 2: per-row combine (threads 0..63), block-min ----
    float bound = 1e30f;
    if (t < 64) {
        float dsum = 0.f, rsum = 0.f;
        #pragma unroll
        for (int qq = 0; qq < 16; qq++) {
            dsum += P[t][qq][0];
            rsum += P[t][qq][1];
        }
        #pragma unroll
        for (int gg = 0; gg < 8; gg++) rsum += colP[gg][t];
        bound = dsum - 0.6f - rsum;      // P_tt lower bound minus radius
    }
    #pragma unroll
    for (int o = 16; o > 0; o >>= 1)
        bound = fminf(bound, __shfl_xor_sync(0xffffffffu, bound, o));
    if ((t & 31) == 0) warpmin[t >> 5] = bound;
    __syncthreads();
    if (t == 0) {
        float mn = fminf(fminf(warpmin[0], warpmin[1]),
                         fminf(warpmin[2], warpmin[3]));
        g_flag[b] = (mn < 0.05f) ? 1 : 0;    // 0.05 = fp-rounding slack
    }
}

// ============================================================================
// Kernel 2 (fallback, gated): warp-per-matrix Householder + Sturm lambda_2.
// Runs only for flagged matrices; contributes relu(0.1-lambda2)/B atomically.
// ============================================================================
__global__ void __launch_bounds__(32 * WPC)
spectral_solve_kernel(const float* __restrict__ E, float* __restrict__ out, int B)
{
    const int lane = threadIdx.x & 31;
    const int w    = threadIdx.x >> 5;
    const int b    = blockIdx.x * WPC + w;
    if (b >= B) return;
    if (g_flag[b] == 0) return;

    __shared__ __align__(16) float sv [WPC][64];
    __shared__ __align__(16) float sw_[WPC][64];
    __shared__ float sdd[WPC][64];
    __shared__ float see[WPC][64];

    const int rL = lane, rH = lane + 32;
    const float* Eb = E + (size_t)b * 4096;

    float aL[64], aH[64];

    float degL = 0.f, degH = 0.f, dsL = 0.f, dsH = 0.f;
    #pragma unroll
    for (int j0 = 0; j0 < 64; j0 += 4) {
        float4 eL = *(const float4*)(Eb + (size_t)rL * 64 + j0);
        float4 eH = *(const float4*)(Eb + (size_t)rH * 64 + j0);
        float s;
        s = sg(eL.x); degL += s; if (j0+0 <  rL) aL[j0+0] = -s; if (j0+0 == rL) dsL = s;
        s = sg(eL.y); degL += s; if (j0+1 <  rL) aL[j0+1] = -s; if (j0+1 == rL) dsL = s;
        s = sg(eL.z); degL += s; if (j0+2 <  rL) aL[j0+2] = -s; if (j0+2 == rL) dsL = s;
        s = sg(eL.w); degL += s; if (j0+3 <  rL) aL[j0+3] = -s; if (j0+3 == rL) dsL = s;
        s = sg(eH.x); degH += s; if (j0+0 <  rH) aH[j0+0] = -s; if (j0+0 == rH) dsH = s;
        s = sg(eH.y); degH += s; if (j0+1 <  rH) aH[j0+1] = -s; if (j0+1 == rH) dsH = s;
        s = sg(eH.z); degH += s; if (j0+2 <  rH) aH[j0+2] = -s; if (j0+2 == rH) dsH = s;
        s = sg(eH.w); degH += s; if (j0+3 <  rH) aH[j0+3] = -s; if (j0+3 == rH) dsH = s;
    }
    #pragma unroll
    for (int j = 1; j < 64; j++) {
        float eu = Eb[(size_t)j * 64 + rL];
        if (j > rL) aL[j] = -sg(eu);
        if (j >= 33) {
            float eu2 = Eb[(size_t)j * 64 + rH];
            if (j > rH) aH[j] = -sg(eu2);
        }
    }
    {
        float dL = degL - dsL, dH = degH - dsH;
        #pragma unroll
        for (int j = 0; j < 64; j++) {
            if (j == rL) aL[j] = dL;
            if (j == rH) aH[j] = dH;
        }
    }

    float xiL = aL[0];
    float xiH = aH[0];

    for (int k = 0; k < 62; k++) {
        const int m0 = k + 1;

        float cL = (rL >= m0) ? xiL : 0.f;
        float cH = (rH >= m0) ? xiH : 0.f;
        float sig = cL * cL + cH * cH;
        #pragma unroll
        for (int o = 16; o > 0; o >>= 1) sig += __shfl_xor_sync(0xffffffffu, sig, o);

        float cand = (m0 < 32) ? xiL : xiH;
        float x0 = __shfl_sync(0xffffffffu, cand, m0 & 31);

        float normx = sqrtf(sig);
        bool  skip  = (normx < 1e-18f);
        float alpha = (x0 >= 0.f) ? -normx : normx;
        float beta  = skip ? 0.f : 1.f / (normx * (normx + fabsf(x0)));

        if (lane == 0) see[w][k] = skip ? 0.f : alpha;
        if (rL == k)   sdd[w][k] = xiL;
        if (rH == k)   sdd[w][k] = xiH;

        float vL = (rL > m0) ? xiL : ((rL == m0) ? (x0 - alpha) : 0.f);
        float vH = (rH > m0) ? xiH : ((rH == m0) ? (x0 - alpha) : 0.f);
        sv[w][rL] = vL;
        sv[w][rH] = vH;
        __syncwarp();

        const int c0 = m0 >> 4;
        float pL0 = 0.f, pL1 = 0.f, pH0 = 0.f, pH1 = 0.f;
        #pragma unroll
        for (int c = 0; c < 4; c++) {
            if (c >= c0) {
                #pragma unroll
                for (int u = 0; u < 16; u += 4) {
                    const int j = 16 * c + u;
                    float4 v4 = *(const float4*)&sv[w][j];
                    pL0 += aL[j]     * v4.x + aL[j + 1] * v4.y;
                    pL1 += aL[j + 2] * v4.z + aL[j + 3] * v4.w;
                    pH0 += aH[j]     * v4.x + aH[j + 1] * v4.y;
                    pH1 += aH[j + 2] * v4.z + aH[j + 3] * v4.w;
                }
            }
        }
        float pL = (rL >= m0) ? (pL0 + pL1) * beta : 0.f;
        float pH = (rH >= m0) ? (pH0 + pH1) * beta : 0.f;

        float Ks = vL * pL + vH * pH;
        #pragma unroll
        for (int o = 16; o > 0; o >>= 1) Ks += __shfl_xor_sync(0xffffffffu, Ks, o);
        float K  = 0.5f * Ks;
        float wL = pL - K * vL;
        float wH = pH - K * vH;
        __syncwarp();
        sw_[w][rL] = wL;
        sw_[w][rH] = wH;
        __syncwarp();

        float nL = 0.f, nH = 0.f;
        #pragma unroll
        for (int c = 0; c < 4; c++) {
            if (c >= c0) {
                #pragma unroll
                for (int u = 0; u < 16; u += 4) {
                    const int j = 16 * c + u;
                    float4 v4 = *(const float4*)&sv[w][j];
                    float4 w4 = *(const float4*)&sw_[w][j];
                    float x;
                    x = aL[j]   - (vL * w4.x + wL * v4.x); aL[j]   = x; if (j     == m0) nL = x;
                    x = aL[j+1] - (vL * w4.y + wL * v4.y); aL[j+1] = x; if (j + 1 == m0) nL = x;
                    x = aL[j+2] - (vL * w4.z + wL * v4.z); aL[j+2] = x; if (j + 2 == m0) nL = x;
                    x = aL[j+3] - (vL * w4.w + wL * v4.w); aL[j+3] = x; if (j + 3 == m0) nL = x;
                    x = aH[j]   - (vH * w4.x + wH * v4.x); aH[j]   = x; if (j     == m0) nH = x;
                    x = aH[j+1] - (vH * w4.y + wH * v4.y); aH[j+1] = x; if (j + 1 == m0) nH = x;
                    x = aH[j+2] - (vH * w4.z + wH * v4.z); aH[j+2] = x; if (j + 2 == m0) nH = x;
                    x = aH[j+3] - (vH * w4.w + wH * v4.w); aH[j+3] = x; if (j + 3 == m0) nH = x;
                }
            }
        }
        xiL = nL;
        xiH = nH;
        __syncwarp();
    }

    if (rH == 62) sdd[w][62] = xiH;
    if (rH == 63) {
        see[w][62] = xiH;
        sdd[w][63] = aH[63];
        see[w][63] = 0.f;
    }
    __syncwarp();

    sw_[w][rL] = see[w][rL] * see[w][rL];
    sw_[w][rH] = see[w][rH] * see[w][rH];
    __syncwarp();

    float dLv = sdd[w][rL], dHv = sdd[w][rH];
    float radL = ((rL > 0) ? fabsf(see[w][rL - 1]) : 0.f) + fabsf(see[w][rL]);
    float radH = fabsf(see[w][rH - 1]) + ((rH < 63) ? fabsf(see[w][rH]) : 0.f);
    float lo = fminf(dLv - radL, dHv - radH);
    float hi = fmaxf(dLv + radL, dHv + radH);
    #pragma unroll
    for (int o = 16; o > 0; o >>= 1) {
        lo = fminf(lo, __shfl_xor_sync(0xffffffffu, lo, o));
        hi = fmaxf(hi, __shfl_xor_sync(0xffffffffu, hi, o));
    }

    #pragma unroll 1
    for (int round = 0; round < 5; round++) {
        float stepw = (hi - lo) * (1.f / 33.f);
        float x = lo + stepw * (float)(lane + 1);
        int cnt = 0;
        float q = sdd[w][0] - x;
        if (q < 0.f) cnt++;
        #pragma unroll 1
        for (int i = 1; i < 64; i++) {
            float denom = q;
            if (fabsf(denom) < 1e-25f) denom = (denom < 0.f) ? -1e-25f : 1e-25f;
            q = (sdd[w][i] - x) - __fdividef(sw_[w][i - 1], denom);
            if (q < 0.f) cnt++;
        }
        unsigned bal = __ballot_sync(0xffffffffu, cnt >= 2);
        if (bal == 0u) {
            lo = lo + stepw * 32.f;
        } else {
            int j = __ffs(bal) - 1;
            float nhi = lo + stepw * (float)(j + 1);
            float nlo = (j > 0) ? (lo + stepw * (float)j) : lo;
            hi = nhi; lo = nlo;
        }
    }
    if (lane == 0) {
        float lam2 = 0.5f * (lo + hi);
        float p = 0.1f - lam2;
        if (p > 0.f) atomicAdd(out, p / (float)B);
    }
}

extern "C" void kernel_launch(void* const* d_in, const int* in_sizes, int n_in,
                              void* d_out, int out_size)
{
    const float* E = (const float*)d_in[0];
    int B = in_sizes[0] / 4096;
    if (B > MAXB) B = MAXB;

    cudaMemsetAsync(d_out, 0, sizeof(float));   // out = 0; fallback adds rare terms
    certify_kernel<<<B, 128>>>(E, B);
    int grid2 = (B + WPC - 1) / WPC;
    spectral_solve_kernel<<<grid2, 32 * WPC>>>(E, (float*)d_out, B);
}

// round 9
// speedup vs baseline: 71.6523x; 1.1037x over previous
#include <cuda_runtime.h>
#include <cuda_bf16.h>
#include <math.h>

#define MAXB 8192

__device__ int g_flag[MAXB];

__device__ __forceinline__ float sg(float x) { return 1.f / (1.f + __expf(-x)); }

// ============================================================================
// Kernel 1: transcendental-free certificate that lambda_2 >= 0.1, single pass.
//
// M = lower-symmetrized (diag(deg) - sigmoid(E));  P = (M - 0.1I) + 0.5*ones*ones^T.
// lambda_1(P) <= lambda_2(M - 0.1I)  (positive rank-1 interlacing).
// Gershgorin row bound on P with piecewise-linear sigmoid bounds:
//   deg_t >= sum_j clamp(0.5 + E[t][j]/4, 0, 0.5)
//   |0.5 - sigma(x)| <= min(|x|/4, 0.5)
//   sigma_tt <= 1
// If min_t bound_t >= 0 (with fp slack) then penalty = 0 exactly; otherwise the
// matrix is flagged for the exact eigensolver fallback.
// Also zeroes out[0] (replaces a memset node; stream order precedes fallback).
// ============================================================================
__global__ void __launch_bounds__(128, 8)
certify_kernel(const float* __restrict__ E, float* __restrict__ out, int B)
{
    const int b = blockIdx.x;
    const int t = threadIdx.x;
    if (b == 0 && t == 0) out[0] = 0.f;
    if (b >= B) return;

    const int q = t & 15;    // column quad: columns 4q..4q+3
    const int g = t >> 4;    // row group 0..7: rows 8i+g

    __shared__ float P[64][17][2];   // [row][q][{deg,rad}]
    __shared__ float colP[8][64];    // [g][col] partial column radii
    __shared__ float warpmin[4];

    const float* Eb = E + (size_t)b * 4096;
    const float4* E4 = (const float4*)Eb;
    const int c0 = 4 * q;

    float col0 = 0.f, col1 = 0.f, col2 = 0.f, col3 = 0.f;

    #pragma unroll
    for (int i = 0; i < 8; i++) {
        float4 v = E4[i * 128 + t];          // fully coalesced
        const int r = 8 * i + g;
        float dacc = 0.f, racc = 0.f;
        float t1, m;

        t1 = fmaf(0.25f, v.x, 0.5f);
        dacc += fminf(fmaxf(t1, 0.f), 0.5f);
        m = fminf(fabsf(t1 - 0.5f), 0.5f);
        if (r > c0 + 0) { racc += m; col0 += m; }

        t1 = fmaf(0.25f, v.y, 0.5f);
        dacc += fminf(fmaxf(t1, 0.f), 0.5f);
        m = fminf(fabsf(t1 - 0.5f), 0.5f);
        if (r > c0 + 1) { racc += m; col1 += m; }

        t1 = fmaf(0.25f, v.z, 0.5f);
        dacc += fminf(fmaxf(t1, 0.f), 0.5f);
        m = fminf(fabsf(t1 - 0.5f), 0.5f);
        if (r > c0 + 2) { racc += m; col2 += m; }

        t1 = fmaf(0.25f, v.w, 0.5f);
        dacc += fminf(fmaxf(t1, 0.f), 0.5f);
        m = fminf(fabsf(t1 - 0.5f), 0.5f);
        if (r > c0 + 3) { racc += m; col3 += m; }

        P[r][q][0] = dacc;
        P[r][q][1] = racc;
    }
    colP[g][c0 + 0] = col0;
    colP[g][c0 + 1] = col1;
    colP[g][c0 + 2] = col2;
    colP[g][c0 + 3] = col3;
    __syncthreads();

    float bound = 1e30f;
    if (t < 64) {
        float dsum = 0.f, rsum = 0.f;
        #pragma unroll
        for (int qq = 0; qq < 16; qq++) {
            dsum += P[t][qq][0];
            rsum += P[t][qq][1];
        }
        #pragma unroll
        for (int gg = 0; gg < 8; gg++) rsum += colP[gg][t];
        bound = dsum - 0.6f - rsum;
    }
    #pragma unroll
    for (int o = 16; o > 0; o >>= 1)
        bound = fminf(bound, __shfl_xor_sync(0xffffffffu, bound, o));
    if ((t & 31) == 0) warpmin[t >> 5] = bound;
    __syncthreads();
    if (t == 0) {
        float mn = fminf(fminf(warpmin[0], warpmin[1]),
                         fminf(warpmin[2], warpmin[3]));
        g_flag[b] = (mn < 0.05f) ? 1 : 0;    // 0.05 = fp-rounding slack
    }
}

// ============================================================================
// Warp-collective exact solver for one flagged matrix:
// Householder tridiagonalization in registers + Sturm multisection lambda_2.
// ============================================================================
__device__ __noinline__ void solve_one_warp(
    const float* __restrict__ Eb, float* __restrict__ out, int B,
    int lane, int w,
    float sv[][64], float sw_[][64], float sdd[][64], float see[][64])
{
    const int rL = lane, rH = lane + 32;
    float aL[64], aH[64];

    float degL = 0.f, degH = 0.f, dsL = 0.f, dsH = 0.f;
    #pragma unroll
    for (int j0 = 0; j0 < 64; j0 += 4) {
        float4 eL = *(const float4*)(Eb + (size_t)rL * 64 + j0);
        float4 eH = *(const float4*)(Eb + (size_t)rH * 64 + j0);
        float s;
        s = sg(eL.x); degL += s; if (j0+0 <  rL) aL[j0+0] = -s; if (j0+0 == rL) dsL = s;
        s = sg(eL.y); degL += s; if (j0+1 <  rL) aL[j0+1] = -s; if (j0+1 == rL) dsL = s;
        s = sg(eL.z); degL += s; if (j0+2 <  rL) aL[j0+2] = -s; if (j0+2 == rL) dsL = s;
        s = sg(eL.w); degL += s; if (j0+3 <  rL) aL[j0+3] = -s; if (j0+3 == rL) dsL = s;
        s = sg(eH.x); degH += s; if (j0+0 <  rH) aH[j0+0] = -s; if (j0+0 == rH) dsH = s;
        s = sg(eH.y); degH += s; if (j0+1 <  rH) aH[j0+1] = -s; if (j0+1 == rH) dsH = s;
        s = sg(eH.z); degH += s; if (j0+2 <  rH) aH[j0+2] = -s; if (j0+2 == rH) dsH = s;
        s = sg(eH.w); degH += s; if (j0+3 <  rH) aH[j0+3] = -s; if (j0+3 == rH) dsH = s;
    }
    #pragma unroll
    for (int j = 1; j < 64; j++) {
        float eu = Eb[(size_t)j * 64 + rL];
        if (j > rL) aL[j] = -sg(eu);
        if (j >= 33) {
            float eu2 = Eb[(size_t)j * 64 + rH];
            if (j > rH) aH[j] = -sg(eu2);
        }
    }
    {
        float dL = degL - dsL, dH = degH - dsH;
        #pragma unroll
        for (int j = 0; j < 64; j++) {
            if (j == rL) aL[j] = dL;
            if (j == rH) aH[j] = dH;
        }
    }

    float xiL = aL[0];
    float xiH = aH[0];

    for (int k = 0; k < 62; k++) {
        const int m0 = k + 1;

        float cL = (rL >= m0) ? xiL : 0.f;
        float cH = (rH >= m0) ? xiH : 0.f;
        float sig = cL * cL + cH * cH;
        #pragma unroll
        for (int o = 16; o > 0; o >>= 1) sig += __shfl_xor_sync(0xffffffffu, sig, o);

        float cand = (m0 < 32) ? xiL : xiH;
        float x0 = __shfl_sync(0xffffffffu, cand, m0 & 31);

        float normx = sqrtf(sig);
        bool  skip  = (normx < 1e-18f);
        float alpha = (x0 >= 0.f) ? -normx : normx;
        float beta  = skip ? 0.f : 1.f / (normx * (normx + fabsf(x0)));

        if (lane == 0) see[w][k] = skip ? 0.f : alpha;
        if (rL == k)   sdd[w][k] = xiL;
        if (rH == k)   sdd[w][k] = xiH;

        float vL = (rL > m0) ? xiL : ((rL == m0) ? (x0 - alpha) : 0.f);
        float vH = (rH > m0) ? xiH : ((rH == m0) ? (x0 - alpha) : 0.f);
        sv[w][rL] = vL;
        sv[w][rH] = vH;
        __syncwarp();

        const int c0 = m0 >> 4;
        float pL0 = 0.f, pL1 = 0.f, pH0 = 0.f, pH1 = 0.f;
        #pragma unroll
        for (int c = 0; c < 4; c++) {
            if (c >= c0) {
                #pragma unroll
                for (int u = 0; u < 16; u += 4) {
                    const int j = 16 * c + u;
                    float4 v4 = *(const float4*)&sv[w][j];
                    pL0 += aL[j]     * v4.x + aL[j + 1] * v4.y;
                    pL1 += aL[j + 2] * v4.z + aL[j + 3] * v4.w;
                    pH0 += aH[j]     * v4.x + aH[j + 1] * v4.y;
                    pH1 += aH[j + 2] * v4.z + aH[j + 3] * v4.w;
                }
            }
        }
        float pL = (rL >= m0) ? (pL0 + pL1) * beta : 0.f;
        float pH = (rH >= m0) ? (pH0 + pH1) * beta : 0.f;

        float Ks = vL * pL + vH * pH;
        #pragma unroll
        for (int o = 16; o > 0; o >>= 1) Ks += __shfl_xor_sync(0xffffffffu, Ks, o);
        float K  = 0.5f * Ks;
        float wL = pL - K * vL;
        float wH = pH - K * vH;
        __syncwarp();
        sw_[w][rL] = wL;
        sw_[w][rH] = wH;
        __syncwarp();

        float nL = 0.f, nH = 0.f;
        #pragma unroll
        for (int c = 0; c < 4; c++) {
            if (c >= c0) {
                #pragma unroll
                for (int u = 0; u < 16; u += 4) {
                    const int j = 16 * c + u;
                    float4 v4 = *(const float4*)&sv[w][j];
                    float4 w4 = *(const float4*)&sw_[w][j];
                    float x;
                    x = aL[j]   - (vL * w4.x + wL * v4.x); aL[j]   = x; if (j     == m0) nL = x;
                    x = aL[j+1] - (vL * w4.y + wL * v4.y); aL[j+1] = x; if (j + 1 == m0) nL = x;
                    x = aL[j+2] - (vL * w4.z + wL * v4.z); aL[j+2] = x; if (j + 2 == m0) nL = x;
                    x = aL[j+3] - (vL * w4.w + wL * v4.w); aL[j+3] = x; if (j + 3 == m0) nL = x;
                    x = aH[j]   - (vH * w4.x + wH * v4.x); aH[j]   = x; if (j     == m0) nH = x;
                    x = aH[j+1] - (vH * w4.y + wH * v4.y); aH[j+1] = x; if (j + 1 == m0) nH = x;
                    x = aH[j+2] - (vH * w4.z + wH * v4.z); aH[j+2] = x; if (j + 2 == m0) nH = x;
                    x = aH[j+3] - (vH * w4.w + wH * v4.w); aH[j+3] = x; if (j + 3 == m0) nH = x;
                }
            }
        }
        xiL = nL;
        xiH = nH;
        __syncwarp();
    }

    if (rH == 62) sdd[w][62] = xiH;
    if (rH == 63) {
        see[w][62] = xiH;
        sdd[w][63] = aH[63];
        see[w][63] = 0.f;
    }
    __syncwarp();

    sw_[w][rL] = see[w][rL] * see[w][rL];
    sw_[w][rH] = see[w][rH] * see[w][rH];
    __syncwarp();

    float dLv = sdd[w][rL], dHv = sdd[w][rH];
    float radL = ((rL > 0) ? fabsf(see[w][rL - 1]) : 0.f) + fabsf(see[w][rL]);
    float radH = fabsf(see[w][rH - 1]) + ((rH < 63) ? fabsf(see[w][rH]) : 0.f);
    float lo = fminf(dLv - radL, dHv - radH);
    float hi = fmaxf(dLv + radL, dHv + radH);
    #pragma unroll
    for (int o = 16; o > 0; o >>= 1) {
        lo = fminf(lo, __shfl_xor_sync(0xffffffffu, lo, o));
        hi = fmaxf(hi, __shfl_xor_sync(0xffffffffu, hi, o));
    }

    #pragma unroll 1
    for (int round = 0; round < 5; round++) {
        float stepw = (hi - lo) * (1.f / 33.f);
        float x = lo + stepw * (float)(lane + 1);
        int cnt = 0;
        float q = sdd[w][0] - x;
        if (q < 0.f) cnt++;
        #pragma unroll 1
        for (int i = 1; i < 64; i++) {
            float denom = q;
            if (fabsf(denom) < 1e-25f) denom = (denom < 0.f) ? -1e-25f : 1e-25f;
            q = (sdd[w][i] - x) - __fdividef(sw_[w][i - 1], denom);
            if (q < 0.f) cnt++;
        }
        unsigned bal = __ballot_sync(0xffffffffu, cnt >= 2);
        if (bal == 0u) {
            lo = lo + stepw * 32.f;
        } else {
            int j = __ffs(bal) - 1;
            float nhi = lo + stepw * (float)(j + 1);
            float nlo = (j > 0) ? (lo + stepw * (float)j) : lo;
            hi = nhi; lo = nlo;
        }
    }
    if (lane == 0) {
        float lam2 = 0.5f * (lo + hi);
        float p = 0.1f - lam2;
        if (p > 0.f) atomicAdd(out, p / (float)B);
    }
}

// ============================================================================
// Kernel 2: tiny fallback dispatcher. 16 CTAs x 4 warps; each warp scans its
// 64 flags (two coalesced L1-bypassing loads issued back-to-back for MLP=2),
// ballots, and solves only set bits (rare/never on this distribution).
// ============================================================================
__global__ void __launch_bounds__(128)
spectral_fallback_kernel(const float* __restrict__ E, float* __restrict__ out, int B)
{
    __shared__ __align__(16) float sv [4][64];
    __shared__ __align__(16) float sw_[4][64];
    __shared__ float sdd[4][64];
    __shared__ float see[4][64];

    const int lane = threadIdx.x & 31;
    const int w    = threadIdx.x >> 5;                    // local warp 0..3
    const int gw   = blockIdx.x * 4 + w;                  // global warp 0..63

    for (int base = gw * 64; base < B; base += 64 * 64) {
        int b0 = base + lane;
        int b1 = base + 32 + lane;
        int f0 = (b0 < B) ? __ldcg(&g_flag[b0]) : 0;      // both loads in flight
        int f1 = (b1 < B) ? __ldcg(&g_flag[b1]) : 0;      // before any ballot
        unsigned bal0 = __ballot_sync(0xffffffffu, f0 != 0);
        unsigned bal1 = __ballot_sync(0xffffffffu, f1 != 0);
        while (bal0) {
            int j = __ffs(bal0) - 1;
            bal0 &= bal0 - 1;
            solve_one_warp(E + (size_t)(base + j) * 4096, out, B, lane, w,
                           sv, sw_, sdd, see);
        }
        while (bal1) {
            int j = __ffs(bal1) - 1;
            bal1 &= bal1 - 1;
            solve_one_warp(E + (size_t)(base + 32 + j) * 4096, out, B, lane, w,
                           sv, sw_, sdd, see);
        }
    }
}

extern "C" void kernel_launch(void* const* d_in, const int* in_sizes, int n_in,
                              void* d_out, int out_size)
{
    const float* E = (const float*)d_in[0];
    int B = in_sizes[0] / 4096;
    if (B > MAXB) B = MAXB;

    certify_kernel<<<B, 128>>>(E, (float*)d_out, B);
    spectral_fallback_kernel<<<16, 128>>>(E, (float*)d_out, B);
}